// round 12
// baseline (speedup 1.0000x reference)
#include <cuda_runtime.h>
#include <stdint.h>

#define BN    64
#define FOUTN 128
#define LDW   136
#define LDSC  68
#define LDADJ 68
#define EPSV 1e-5f
#define SLOPEV 0.01f

// shared layout (float words)
#define OFF_HF   0                    // 6144  : h A-frag (nks=12) tf32
#define OFF_W1   6144                 // 12288 : W B-frag -> {Wopd,Wopg B-frag} -> {wa A-frag, attn A-frag}
#define OFF_W2   18432                // 12288 : Wk B-frag -> {adj std, adj A-frag, op A-frag}
#define OFF_SUP  30720                // 8704  : fp32 support -> dense (std, LDW)
#define OFF_WHK  39424                // 8704  : fp32 Whk -> hp (std, LDW)
#define OFF_SC   48128                // 4352  : fp32 scores (std, LDSC)
#define OFF_AW   52480
#define OFF_B    52608
#define OFF_BD   52736
#define OFF_BG   52864
#define OFF_MU   52992
#define OFF_RS   53056
#define SMEM_FLOATS 53120             // 212480 bytes

// overlaid sub-regions
#define OFF_WOPD (OFF_W1)             // 6144  B-frag nks=6
#define OFF_WOPG (OFF_W1 + 6144)      // 6144  B-frag nks=6
#define OFF_WA   (OFF_W1)             // 8192  A-frag nks=16 (tf32)
#define OFF_ATT  (OFF_W1 + 8192)      // 4096  A-frag nks=8  (tf32)
#define OFF_ADJS (OFF_W2)             // 4352  std tf32 bits (LDADJ)
#define OFF_ADJF (OFF_W2 + 4352)      // 4096  A-frag nks=8
#define OFF_OPF  (OFF_W2 + 8448)      // 3072  A-frag nks=6

__device__ __forceinline__ uint32_t f2tf(float f) {
    uint32_t u;
    asm("cvt.rna.tf32.f32 %0, %1;" : "=r"(u) : "f"(f));
    return u;
}

__device__ __forceinline__ void mma_tf32(float c[4],
                                         uint32_t a0, uint32_t a1, uint32_t a2, uint32_t a3,
                                         uint32_t b0, uint32_t b1) {
    asm volatile(
        "mma.sync.aligned.m16n8k8.row.col.f32.tf32.tf32.f32 "
        "{%0,%1,%2,%3}, {%4,%5,%6,%7}, {%8,%9}, {%0,%1,%2,%3};"
        : "+f"(c[0]), "+f"(c[1]), "+f"(c[2]), "+f"(c[3])
        : "r"(a0), "r"(a1), "r"(a2), "r"(a3), "r"(b0), "r"(b1));
}

// A-fragment address: value A[r][c] for m16n8k8 A-frag (a0..a3 order).
// Layout: [panel r>>4][ks=c>>3][lane=(r&7)*4+(c&3)][e=2*((c>>2)&1)+((r>>3)&1)]
__device__ __forceinline__ int afrag(int r, int c, int nks) {
    int lane = ((r & 7) << 2) | (c & 3);
    return ((r >> 4) * nks + (c >> 3)) * 128 + (lane << 2)
         + (((c >> 2) & 1) << 1) + ((r >> 3) & 1);
}

// B-fragment address: value B[k][n].
// Layout: [panel n>>5][(ks=k>>3)*4 + nb=(n>>3)&3][lane=(n&7)*4+(k&3)][half=(k>>2)&1]
__device__ __forceinline__ int bfrag(int k, int n, int nks) {
    int lane = ((n & 7) << 2) | (k & 3);
    return (n >> 5) * (nks << 8) + ((((k >> 3) << 2) + ((n >> 3) & 3)) << 6)
         + (lane << 1) + ((k >> 2) & 1);
}

__device__ __forceinline__ void store_frag4(float* D, int ldd, int m0, int n0,
                                            int lr, int lc, float acc[4][4]) {
    #pragma unroll
    for (int nb = 0; nb < 4; nb++) {
        int c0 = n0 + nb*8 + 2*lc;
        D[(m0+lr  )*ldd + c0  ] = acc[nb][0];
        D[(m0+lr  )*ldd + c0+1] = acc[nb][1];
        D[(m0+lr+8)*ldd + c0  ] = acc[nb][2];
        D[(m0+lr+8)*ldd + c0+1] = acc[nb][3];
    }
}

__global__ void __launch_bounds__(512, 1)
gin_mma3_kernel(const float* __restrict__ g_h, const float* __restrict__ g_adj,
                const float* __restrict__ g_op,
                const float* __restrict__ g_W,  const float* __restrict__ g_b,
                const float* __restrict__ g_Wopd, const float* __restrict__ g_bopd,
                const float* __restrict__ g_Wk, const float* __restrict__ g_aw,
                const float* __restrict__ g_Wopg, const float* __restrict__ g_bopg,
                const float* __restrict__ g_gamma, const float* __restrict__ g_beta,
                float* __restrict__ g_out)
{
    extern __shared__ float smem[];
    uint32_t* su = reinterpret_cast<uint32_t*>(smem);
    float* sh_sup = smem + OFF_SUP;
    float* sh_whk = smem + OFF_WHK;
    float* sh_sc  = smem + OFF_SC;
    float* sh_aw  = smem + OFF_AW;
    float* sh_b   = smem + OFF_B;
    float* sh_bd  = smem + OFF_BD;
    float* sh_bg  = smem + OFF_BG;
    float* sh_mu  = smem + OFF_MU;
    float* sh_rs  = smem + OFF_RS;

    const int tid  = threadIdx.x;
    const int lane = tid & 31;
    const int w    = tid >> 5;          // 0..15
    const int lr   = lane >> 2;         // 0..7
    const int lc   = lane & 3;          // 0..3
    const int mp   = w & 3;             // A panel
    const int np   = w >> 2;            // B panel
    const int m0   = mp * 16;
    const int n0   = np * 32;
    const int j0   = np * 16;
    const int bb   = blockIdx.x;

    const float* hB   = g_h   + (size_t)bb * BN * 96;
    const float* adjB = g_adj + (size_t)bb * BN * BN;
    const float* opB  = g_op  + (size_t)bb * BN * 48;
    float*       outB = g_out + (size_t)bb * BN * FOUTN;

    // ---- phase A loads: h (A-frag), W/Wk (B-frag), vectors ----
    {
        const float4* h4 = (const float4*)hB;
        for (int i = tid; i < 1536; i += 512) {
            int r = i / 24, c = (i % 24) * 4;
            float4 v = h4[i];
            su[OFF_HF + afrag(r, c+0, 12)] = f2tf(v.x);
            su[OFF_HF + afrag(r, c+1, 12)] = f2tf(v.y);
            su[OFF_HF + afrag(r, c+2, 12)] = f2tf(v.z);
            su[OFF_HF + afrag(r, c+3, 12)] = f2tf(v.w);
        }
        const float4* w4 = (const float4*)g_W;
        const float4* k4 = (const float4*)g_Wk;
        for (int i = tid; i < 3072; i += 512) {
            int k = i / 32, n = (i % 32) * 4;
            float4 v = w4[i], u = k4[i];
            su[OFF_W1 + bfrag(k, n+0, 12)] = f2tf(v.x);
            su[OFF_W1 + bfrag(k, n+1, 12)] = f2tf(v.y);
            su[OFF_W1 + bfrag(k, n+2, 12)] = f2tf(v.z);
            su[OFF_W1 + bfrag(k, n+3, 12)] = f2tf(v.w);
            su[OFF_W2 + bfrag(k, n+0, 12)] = f2tf(u.x);
            su[OFF_W2 + bfrag(k, n+1, 12)] = f2tf(u.y);
            su[OFF_W2 + bfrag(k, n+2, 12)] = f2tf(u.z);
            su[OFF_W2 + bfrag(k, n+3, 12)] = f2tf(u.w);
        }
        if (tid < 128) {
            sh_aw[tid] = g_aw[tid];
            sh_b[tid]  = g_b[tid];
            sh_bd[tid] = g_bopd[tid];
            sh_bg[tid] = g_bopg[tid];
        }
    }
    __syncthreads();

    // ---- fused: support = h@W, Whk = h@Wk ----
    {
        float acc1[4][4], acc2[4][4];
        #pragma unroll
        for (int a = 0; a < 4; a++)
            #pragma unroll
            for (int t = 0; t < 4; t++) { acc1[a][t] = 0.f; acc2[a][t] = 0.f; }
        const uint32_t* Hf = su + OFF_HF + mp * 1536;
        const uint32_t* Wf = su + OFF_W1 + np * 3072;
        const uint32_t* Kf = su + OFF_W2 + np * 3072;
        #pragma unroll
        for (int ks = 0; ks < 12; ks++) {
            uint4 a = *(const uint4*)(Hf + ks*128 + lane*4);
            #pragma unroll
            for (int nb = 0; nb < 4; nb++) {
                uint2 b = *(const uint2*)(Wf + (ks*4+nb)*64 + lane*2);
                mma_tf32(acc1[nb], a.x, a.y, a.z, a.w, b.x, b.y);
                uint2 c2 = *(const uint2*)(Kf + (ks*4+nb)*64 + lane*2);
                mma_tf32(acc2[nb], a.x, a.y, a.z, a.w, c2.x, c2.y);
            }
        }
        store_frag4(sh_sup, LDW, m0, n0, lr, lc, acc1);
        store_frag4(sh_whk, LDW, m0, n0, lr, lc, acc2);
    }
    __syncthreads();   // W1/W2 dead; sup/whk visible

    // ---- phase B loads: Wopd/Wopg (B-frag) -> W1; adj(std+A-frag), op(A-frag) -> W2 ----
    {
        const float4* d4 = (const float4*)g_Wopd;
        const float4* g4 = (const float4*)g_Wopg;
        for (int i = tid; i < 1536; i += 512) {
            int k = i / 32, n = (i % 32) * 4;
            float4 v = d4[i], u = g4[i];
            su[OFF_WOPD + bfrag(k, n+0, 6)] = f2tf(v.x);
            su[OFF_WOPD + bfrag(k, n+1, 6)] = f2tf(v.y);
            su[OFF_WOPD + bfrag(k, n+2, 6)] = f2tf(v.z);
            su[OFF_WOPD + bfrag(k, n+3, 6)] = f2tf(v.w);
            su[OFF_WOPG + bfrag(k, n+0, 6)] = f2tf(u.x);
            su[OFF_WOPG + bfrag(k, n+1, 6)] = f2tf(u.y);
            su[OFF_WOPG + bfrag(k, n+2, 6)] = f2tf(u.z);
            su[OFF_WOPG + bfrag(k, n+3, 6)] = f2tf(u.w);
        }
        const float4* a4 = (const float4*)adjB;
        for (int i = tid; i < 1024; i += 512) {
            int r = i / 16, c = (i % 16) * 4;
            float4 v = a4[i];
            uint32_t t0 = f2tf(v.x), t1 = f2tf(v.y), t2 = f2tf(v.z), t3 = f2tf(v.w);
            su[OFF_ADJS + r*LDADJ + c+0] = t0;
            su[OFF_ADJS + r*LDADJ + c+1] = t1;
            su[OFF_ADJS + r*LDADJ + c+2] = t2;
            su[OFF_ADJS + r*LDADJ + c+3] = t3;
            su[OFF_ADJF + afrag(r, c+0, 8)] = t0;
            su[OFF_ADJF + afrag(r, c+1, 8)] = t1;
            su[OFF_ADJF + afrag(r, c+2, 8)] = t2;
            su[OFF_ADJF + afrag(r, c+3, 8)] = t3;
        }
        const float4* o4 = (const float4*)opB;
        for (int i = tid; i < 768; i += 512) {
            int r = i / 12, c = (i % 12) * 4;
            float4 v = o4[i];
            su[OFF_OPF + afrag(r, c+0, 6)] = f2tf(v.x);
            su[OFF_OPF + afrag(r, c+1, 6)] = f2tf(v.y);
            su[OFF_OPF + afrag(r, c+2, 6)] = f2tf(v.z);
            su[OFF_OPF + afrag(r, c+3, 6)] = f2tf(v.w);
        }
    }
    __syncthreads();

    // ---- gates ----
    float gdv[4][4], ggv[4][4];
    {
        #pragma unroll
        for (int a = 0; a < 4; a++)
            #pragma unroll
            for (int t = 0; t < 4; t++) { gdv[a][t] = 0.f; ggv[a][t] = 0.f; }
        const uint32_t* Of = su + OFF_OPF  + mp * 768;
        const uint32_t* Df = su + OFF_WOPD + np * 1536;
        const uint32_t* Gf = su + OFF_WOPG + np * 1536;
        #pragma unroll
        for (int ks = 0; ks < 6; ks++) {
            uint4 a = *(const uint4*)(Of + ks*128 + lane*4);
            #pragma unroll
            for (int nb = 0; nb < 4; nb++) {
                uint2 d = *(const uint2*)(Df + (ks*4+nb)*64 + lane*2);
                mma_tf32(gdv[nb], a.x, a.y, a.z, a.w, d.x, d.y);
                uint2 e = *(const uint2*)(Gf + (ks*4+nb)*64 + lane*2);
                mma_tf32(ggv[nb], a.x, a.y, a.z, a.w, e.x, e.y);
            }
        }
        #pragma unroll
        for (int nb = 0; nb < 4; nb++) {
            int cA = n0 + nb*8 + 2*lc, cB = cA + 1;
            gdv[nb][0] = 1.f/(1.f+__expf(-(gdv[nb][0] + sh_bd[cA])));
            gdv[nb][1] = 1.f/(1.f+__expf(-(gdv[nb][1] + sh_bd[cB])));
            gdv[nb][2] = 1.f/(1.f+__expf(-(gdv[nb][2] + sh_bd[cA])));
            gdv[nb][3] = 1.f/(1.f+__expf(-(gdv[nb][3] + sh_bd[cB])));
            ggv[nb][0] = 1.f/(1.f+__expf(-(ggv[nb][0] + sh_bg[cA])));
            ggv[nb][1] = 1.f/(1.f+__expf(-(ggv[nb][1] + sh_bg[cB])));
            ggv[nb][2] = 1.f/(1.f+__expf(-(ggv[nb][2] + sh_bg[cA])));
            ggv[nb][3] = 1.f/(1.f+__expf(-(ggv[nb][3] + sh_bg[cB])));
        }
    }

    // ---- dense = gd * (adj @ support) + support + b ----
    float dnv[4][4];
    {
        #pragma unroll
        for (int a = 0; a < 4; a++)
            #pragma unroll
            for (int t = 0; t < 4; t++) dnv[a][t] = 0.f;
        const uint32_t* Af = su + OFF_ADJF + mp * 1024;
        #pragma unroll
        for (int ks = 0; ks < 8; ks++) {
            uint4 a = *(const uint4*)(Af + ks*128 + lane*4);
            const int k0 = ks * 8;
            #pragma unroll
            for (int nb = 0; nb < 4; nb++) {
                uint32_t b0 = f2tf(sh_sup[(k0+lc  )*LDW + n0+nb*8+lr]);
                uint32_t b1 = f2tf(sh_sup[(k0+lc+4)*LDW + n0+nb*8+lr]);
                mma_tf32(dnv[nb], a.x, a.y, a.z, a.w, b0, b1);
            }
        }
        #pragma unroll
        for (int nb = 0; nb < 4; nb++) {
            int cA = n0 + nb*8 + 2*lc, cB = cA + 1;
            int rA = m0 + lr, rB = m0 + lr + 8;
            dnv[nb][0] = gdv[nb][0]*dnv[nb][0] + sh_sup[rA*LDW + cA] + sh_b[cA];
            dnv[nb][1] = gdv[nb][1]*dnv[nb][1] + sh_sup[rA*LDW + cB] + sh_b[cB];
            dnv[nb][2] = gdv[nb][2]*dnv[nb][2] + sh_sup[rB*LDW + cA] + sh_b[cA];
            dnv[nb][3] = gdv[nb][3]*dnv[nb][3] + sh_sup[rB*LDW + cB] + sh_b[cB];
        }
    }
    __syncthreads();   // sup reads done; W1 (Wop) dead

    // ---- dense -> sup; wa = tf32(whk * a_w) in A-frag order -> W1 ----
    store_frag4(sh_sup, LDW, m0, n0, lr, lc, dnv);
    {
        for (int i = tid; i < BN*FOUTN; i += 512) {
            int r = i >> 7, c = i & 127;
            su[OFF_WA + afrag(r, c, 16)] = f2tf(sh_whk[r*LDW + c] * sh_aw[c]);
        }
    }
    __syncthreads();

    // ---- scores[i][j] = leaky(sum_m wa[i][m]*whk[j][m]) * adj[i][j] ----
    {
        float sc2[2][4];
        #pragma unroll
        for (int a = 0; a < 2; a++)
            #pragma unroll
            for (int t = 0; t < 4; t++) sc2[a][t] = 0.f;
        const uint32_t* Waf = su + OFF_WA + mp * 2048;
        #pragma unroll
        for (int ks = 0; ks < 16; ks++) {
            uint4 a = *(const uint4*)(Waf + ks*128 + lane*4);
            const int k0 = ks * 8;
            #pragma unroll
            for (int nb = 0; nb < 2; nb++) {
                int jrow = j0 + nb*8 + lr;
                uint32_t b0 = f2tf(sh_whk[jrow*LDW + k0+lc  ]);
                uint32_t b1 = f2tf(sh_whk[jrow*LDW + k0+lc+4]);
                mma_tf32(sc2[nb], a.x, a.y, a.z, a.w, b0, b1);
            }
        }
        #pragma unroll
        for (int nb = 0; nb < 2; nb++) {
            int jA = j0 + nb*8 + 2*lc, jB = jA + 1;
            int iA = m0 + lr, iB = m0 + lr + 8;
            float s;
            s = sc2[nb][0]; s = (s >= 0.f) ? s : SLOPEV*s; sh_sc[iA*LDSC + jA] = s * __uint_as_float(su[OFF_ADJS + iA*LDADJ + jA]);
            s = sc2[nb][1]; s = (s >= 0.f) ? s : SLOPEV*s; sh_sc[iA*LDSC + jB] = s * __uint_as_float(su[OFF_ADJS + iA*LDADJ + jB]);
            s = sc2[nb][2]; s = (s >= 0.f) ? s : SLOPEV*s; sh_sc[iB*LDSC + jA] = s * __uint_as_float(su[OFF_ADJS + iB*LDADJ + jA]);
            s = sc2[nb][3]; s = (s >= 0.f) ? s : SLOPEV*s; sh_sc[iB*LDSC + jB] = s * __uint_as_float(su[OFF_ADJS + iB*LDADJ + jB]);
        }
    }
    __syncthreads();

    // ---- softmax over j, 8 threads/row; write attn in A-frag order (tf32) ----
    {
        const int row = tid >> 3;
        const int q   = tid & 7;
        float4 e0 = *(const float4*)&sh_sc[row*LDSC + q*8];
        float4 e1 = *(const float4*)&sh_sc[row*LDSC + q*8 + 4];
        float mx = fmaxf(fmaxf(fmaxf(e0.x,e0.y),fmaxf(e0.z,e0.w)),
                         fmaxf(fmaxf(e1.x,e1.y),fmaxf(e1.z,e1.w)));
        mx = fmaxf(mx, __shfl_xor_sync(0xffffffffu, mx, 1));
        mx = fmaxf(mx, __shfl_xor_sync(0xffffffffu, mx, 2));
        mx = fmaxf(mx, __shfl_xor_sync(0xffffffffu, mx, 4));
        e0.x = __expf(e0.x - mx); e0.y = __expf(e0.y - mx);
        e0.z = __expf(e0.z - mx); e0.w = __expf(e0.w - mx);
        e1.x = __expf(e1.x - mx); e1.y = __expf(e1.y - mx);
        e1.z = __expf(e1.z - mx); e1.w = __expf(e1.w - mx);
        float sum = e0.x+e0.y+e0.z+e0.w+e1.x+e1.y+e1.z+e1.w;
        sum += __shfl_xor_sync(0xffffffffu, sum, 1);
        sum += __shfl_xor_sync(0xffffffffu, sum, 2);
        sum += __shfl_xor_sync(0xffffffffu, sum, 4);
        float inv = 1.f / sum;
        int c0 = q * 8;
        su[OFF_ATT + afrag(row, c0+0, 8)] = f2tf(e0.x * inv);
        su[OFF_ATT + afrag(row, c0+1, 8)] = f2tf(e0.y * inv);
        su[OFF_ATT + afrag(row, c0+2, 8)] = f2tf(e0.z * inv);
        su[OFF_ATT + afrag(row, c0+3, 8)] = f2tf(e0.w * inv);
        su[OFF_ATT + afrag(row, c0+4, 8)] = f2tf(e1.x * inv);
        su[OFF_ATT + afrag(row, c0+5, 8)] = f2tf(e1.y * inv);
        su[OFF_ATT + afrag(row, c0+6, 8)] = f2tf(e1.z * inv);
        su[OFF_ATT + afrag(row, c0+7, 8)] = f2tf(e1.w * inv);
    }
    __syncthreads();

    // ---- hp = gg * (attn @ Whk) ----
    {
        float hpv[4][4];
        #pragma unroll
        for (int a = 0; a < 4; a++)
            #pragma unroll
            for (int t = 0; t < 4; t++) hpv[a][t] = 0.f;
        const uint32_t* Tf = su + OFF_ATT + mp * 1024;
        #pragma unroll
        for (int ks = 0; ks < 8; ks++) {
            uint4 a = *(const uint4*)(Tf + ks*128 + lane*4);
            const int k0 = ks * 8;
            #pragma unroll
            for (int nb = 0; nb < 4; nb++) {
                uint32_t b0 = f2tf(sh_whk[(k0+lc  )*LDW + n0+nb*8+lr]);
                uint32_t b1 = f2tf(sh_whk[(k0+lc+4)*LDW + n0+nb*8+lr]);
                mma_tf32(hpv[nb], a.x, a.y, a.z, a.w, b0, b1);
            }
        }
        #pragma unroll
        for (int nb = 0; nb < 4; nb++)
            #pragma unroll
            for (int t = 0; t < 4; t++) hpv[nb][t] *= ggv[nb][t];
        __syncthreads();   // all reads of sh_whk done
        store_frag4(sh_whk, LDW, m0, n0, lr, lc, hpv);
    }
    __syncthreads();

    // ---- LayerNorm stats (8 threads/row) ----
    {
        const int row = tid >> 3;
        const int q   = tid & 7;
        float sum = 0.f, sq = 0.f;
        #pragma unroll
        for (int c = 0; c < 4; c++) {
            float4 v = *(const float4*)&sh_whk[row*LDW + q*16 + c*4];
            sum += v.x+v.y+v.z+v.w;
            sq  += v.x*v.x + v.y*v.y + v.z*v.z + v.w*v.w;
        }
        sum += __shfl_xor_sync(0xffffffffu, sum, 1);
        sum += __shfl_xor_sync(0xffffffffu, sum, 2);
        sum += __shfl_xor_sync(0xffffffffu, sum, 4);
        sq  += __shfl_xor_sync(0xffffffffu, sq, 1);
        sq  += __shfl_xor_sync(0xffffffffu, sq, 2);
        sq  += __shfl_xor_sync(0xffffffffu, sq, 4);
        float mu  = sum * (1.f / FOUTN);
        float var = sq * (1.f / FOUTN) - mu*mu;
        if (q == 0) { sh_mu[row] = mu; sh_rs[row] = rsqrtf(var + EPSV); }
    }
    __syncthreads();

    // ---- combine & write ----
    {
        const int col4 = lane * 4;
        const int r0v  = w * 4;
        float4 gm = *(const float4*)&g_gamma[col4];
        float4 be = *(const float4*)&g_beta[col4];
        #pragma unroll
        for (int ii = 0; ii < 4; ii++) {
            int r = r0v + ii;
            float mu = sh_mu[r], rs = sh_rs[r];
            float4 v  = *(const float4*)&sh_whk[r*LDW + col4];
            float4 dd = *(const float4*)&sh_sup[r*LDW + col4];
            float4 o;
            o.x = 0.5f*(dd.x + (v.x - mu)*rs*gm.x + be.x);
            o.y = 0.5f*(dd.y + (v.y - mu)*rs*gm.y + be.y);
            o.z = 0.5f*(dd.z + (v.z - mu)*rs*gm.z + be.z);
            o.w = 0.5f*(dd.w + (v.w - mu)*rs*gm.w + be.w);
            *(float4*)&outB[r*FOUTN + col4] = o;
        }
    }
}

extern "C" void kernel_launch(void* const* d_in, const int* in_sizes, int n_in,
                              void* d_out, int out_size)
{
    const float* h     = (const float*)d_in[0];
    const float* adj   = (const float*)d_in[1];
    const float* op    = (const float*)d_in[2];
    const float* W     = (const float*)d_in[3];
    const float* b     = (const float*)d_in[4];
    const float* Wopd  = (const float*)d_in[5];
    const float* bopd  = (const float*)d_in[6];
    const float* Wk    = (const float*)d_in[7];
    const float* aw    = (const float*)d_in[8];
    const float* Wopg  = (const float*)d_in[9];
    const float* bopg  = (const float*)d_in[10];
    const float* gamma = (const float*)d_in[11];
    const float* beta  = (const float*)d_in[12];
    float* out = (float*)d_out;

    const int B = in_sizes[0] / (BN * 96);   // 2048
    const size_t smem_bytes = SMEM_FLOATS * sizeof(float);

    static bool attr_set = false;
    if (!attr_set) {
        cudaFuncSetAttribute(gin_mma3_kernel,
                             cudaFuncAttributeMaxDynamicSharedMemorySize,
                             (int)smem_bytes);
        attr_set = true;
    }

    gin_mma3_kernel<<<B, 512, smem_bytes>>>(h, adj, op, W, b, Wopd, bopd,
                                            Wk, aw, Wopg, bopg, gamma, beta, out);
}